// round 15
// baseline (speedup 1.0000x reference)
#include <cuda_runtime.h>
#include <cuda_bf16.h>

// Seq2seq LSTM via mma.sync.m16n8k16.bf16, split-bf16 (hi+lo, 3 products),
// fp32 accumulation. 128 persistent CTAs = 16 slices x 8 M-groups.
// R15 = R14 + software-pipelined ks loop (fragment double-buffering).

typedef unsigned int u32;
typedef unsigned short u16;

#define HID 256
#define NB  8192
#define PLANE (NB * 128)           // u32 pairs per h plane
#define STR 136                    // u32 row stride (8 mod 32: conflict-free)

__device__ __align__(16) u32 g_Wh[2][1024][128];   // Whh hi pairs
__device__ __align__(16) u32 g_Wl[2][1024][128];   // Whh lo pairs
__device__ __align__(16) u32 g_Wxh[1024][8];       // Wih hi pairs
__device__ __align__(16) u32 g_Wxl[1024][8];       // Wih lo pairs
__device__ __align__(16) u32 g_xT[48 * 128 * 64 * 16]; // x tile images
__device__ __align__(16) u32 g_hHi[2][PLANE];      // h hi pairs, scol'd
__device__ __align__(16) u32 g_hLo[2][PLANE];      // h lo pairs, scol'd
__device__ __align__(16) float g_dWp[24 * 8 * 256];    // dense W, k-permuted
__device__ int g_ctr[16 * 72];

// ---- helpers ---------------------------------------------------------------
__device__ __forceinline__ u32 smem_u32(const void* p) {
    u32 a;
    asm("{ .reg .u64 t; cvta.to.shared.u64 t, %1; cvt.u32.u64 %0, t; }"
        : "=r"(a) : "l"(p));
    return a;
}
__device__ __forceinline__ void cpa16(u32 dst, const void* src) {
    asm volatile("cp.async.cg.shared.global [%0], [%1], 16;"
                 :: "r"(dst), "l"(src));
}
#define CPA_COMMIT() asm volatile("cp.async.commit_group;" ::: "memory")
#define CPA_WAIT0()  asm volatile("cp.async.wait_group 0;" ::: "memory")

__device__ __forceinline__ void mma16816(float* d, u32 a0, u32 a1, u32 a2,
                                         u32 a3, u32 b0, u32 b1) {
    asm volatile(
        "mma.sync.aligned.m16n8k16.row.col.f32.bf16.bf16.f32 "
        "{%0,%1,%2,%3}, {%4,%5,%6,%7}, {%8,%9}, {%0,%1,%2,%3};"
        : "+f"(d[0]), "+f"(d[1]), "+f"(d[2]), "+f"(d[3])
        : "r"(a0), "r"(a1), "r"(a2), "r"(a3), "r"(b0), "r"(b1));
}
__device__ __forceinline__ float sigf(float x) {
    return __fdividef(1.0f, 1.0f + __expf(-x));
}
__device__ __forceinline__ float tanh_(float x) {
    return 1.0f - __fdividef(2.0f, __expf(2.0f * x) + 1.0f);
}
__device__ __forceinline__ void split16(float v, u16& h, u16& l) {
    __nv_bfloat16 hb = __float2bfloat16(v);
    __nv_bfloat16 lb = __float2bfloat16(v - __bfloat162float(hb));
    h = *(u16*)&hb; l = *(u16*)&lb;
}
__device__ __forceinline__ float2 bf2f(u32 v) {
    return __bfloat1622float2(*(__nv_bfloat162*)&v);
}
// pair j -> storage col (scol): (b0,b1) of a fragment = one LDS.64
__device__ __forceinline__ int scol(int j) {
    return (j & ~7) + ((j & 3) << 1) + ((j >> 2) & 1);
}

// ---- SMEM byte layout -------------------------------------------------------
#define OF_BIAS 0
#define OF_AU   1024            // Whi tile 128xSTR u32 = 69632
#define OF_AL   70656           // Wlo tile 69632
#define OF_AX   140288          // Wx tile 128x20 u32 = 10240 (alias: dense W)
#define OF_BX0  150528          // x tile ping 64x20 u32 = 5120
#define OF_BX1  155648          // x tile pong 5120
#define OF_BU   160768          // h_hi tile 64xSTR = 34816 (alias: bounce)
#define OF_BL   195584          // h_lo tile 34816
#define SMEM_BYTES 230400

// ---------------------------------------------------------------------------
__global__ void prep_kernel(const float* __restrict__ x,
                            const float* __restrict__ Wih,
                            const float* __restrict__ Whhe,
                            const float* __restrict__ Whhd,
                            const float* __restrict__ dW)
{
    const int S1 = 2 * 1024 * 128;
    const int S2 = S1 + 1024 * 8;
    const int S3 = S2 + 2 * PLANE;
    const int S4 = S3 + 16 * 72;
    const int S5 = S4 + 48 * 128 * 64 * 8;
    const int S6 = S5 + 24 * 8 * 256;
    for (int i = blockIdx.x * blockDim.x + threadIdx.x; i < S6;
         i += gridDim.x * blockDim.x) {
        if (i < S1) {
            int which = i >> 17, j = i & 131071;
            int G = j >> 7, col = j & 127;
            const float* W = which ? Whhd : Whhe;
            u16 ha, la, hb, lb;
            split16(W[G * HID + 2 * col], ha, la);
            split16(W[G * HID + 2 * col + 1], hb, lb);
            g_Wh[which][G][col] = (u32)ha | ((u32)hb << 16);
            g_Wl[which][G][col] = (u32)la | ((u32)lb << 16);
        } else if (i < S2) {
            int j = i - S1, G = j >> 3, cp = j & 7;
            u16 ha, la, hb, lb;
            split16(Wih[G * 16 + 2 * cp], ha, la);
            split16(Wih[G * 16 + 2 * cp + 1], hb, lb);
            g_Wxh[G][cp] = (u32)ha | ((u32)hb << 16);
            g_Wxl[G][cp] = (u32)la | ((u32)lb << 16);
        } else if (i < S3) {
            int j = i - S2;
            if (j < PLANE) g_hHi[0][j] = 0; else g_hLo[0][j - PLANE] = 0;
        } else if (i < S4) {
            g_ctr[i - S3] = 0;
        } else if (i < S5) {
            int j = i - S4;
            int cp = j & 7, n = (j >> 3) & 63, sq = (j >> 9) & 127, t = j >> 16;
            u16 ha, la, hb, lb;
            int ng = sq * 64 + n;
            split16(x[(ng * 16 + 2 * cp) * 48 + t], ha, la);
            split16(x[(ng * 16 + 2 * cp + 1) * 48 + t], hb, lb);
            int sc = ((cp & 3) << 1) + (cp >> 2);      // scol within 8-group
            u32* dst = g_xT + ((t * 128 + sq) * 64 + n) * 16;
            dst[sc]     = (u32)ha | ((u32)hb << 16);
            dst[8 + sc] = (u32)la | ((u32)lb << 16);
        } else {
            int j = i - S5;
            int k = j & 255, o = (j >> 8) & 7, td = j >> 11;
            g_dWp[td * 2048 + o * 256 + 2 * scol(k >> 1) + (k & 1)] =
                dW[td * 2048 + o * 256 + k];
        }
    }
}

// ---------------------------------------------------------------------------
__device__ __forceinline__ void loadA(int which, int m, int tid, char* sm)
{
    u32* AuHi = (u32*)(sm + OF_AU);
    u32* AuLo = (u32*)(sm + OF_AL);
    u32* Ax   = (u32*)(sm + OF_AX);
    for (int i = tid; i < 128 * 128; i += 512) {
        int r = i >> 7, j = i & 127;
        int G = ((r >> 5) << 8) + (m << 5) + (r & 31);
        int col = scol(j);
        AuHi[r * STR + col] = g_Wh[which][G][j];
        AuLo[r * STR + col] = g_Wl[which][G][j];
    }
    if (which == 0) {
        for (int i = tid; i < 128 * 8; i += 512) {
            int r = i >> 3, j = i & 7;
            int G = ((r >> 5) << 8) + (m << 5) + (r & 31);
            int col = ((j & 3) << 1) + (j >> 2);
            Ax[r * 20 + col]     = g_Wxh[G][j];
            Ax[r * 20 + 8 + col] = g_Wxl[G][j];
        }
    }
}

// cp.async one 32KB h plane tile (64 rows x 128 u32 pairs) into padded tile.
__device__ __forceinline__ void copyPlane(u32 sb, int dstOff,
                                          const u32* __restrict__ src, int tid)
{
    int n = tid >> 3;
    #pragma unroll
    for (int it = 0; it < 4; ++it) {
        int c = (tid & 7) + it * 8;
        cpa16(sb + dstOff + (n * STR + c * 4) * 4, src + n * 128 + c * 4);
    }
}
__device__ __forceinline__ void copyX(u32 sb, int dstOff,
                                      const u32* __restrict__ src, int tid)
{
    if (tid < 256) {
        int n = tid >> 2, c4 = tid & 3;
        cpa16(sb + dstOff + (n * 20 + c4 * 4) * 4, src + n * 16 + c4 * 4);
    }
}

// ---------------------------------------------------------------------------
__global__ void __launch_bounds__(512, 1)
lstm_mma(const float* __restrict__ enc_b, const float* __restrict__ dec_b,
         const float* __restrict__ db, float* __restrict__ out)
{
    extern __shared__ char sm[];
    const u32 sb = smem_u32(sm);
    float* sbias  = (float*)(sm + OF_BIAS);
    u32*   AuHi   = (u32*)(sm + OF_AU);
    u32*   AuLo   = (u32*)(sm + OF_AL);
    u32*   Ax     = (u32*)(sm + OF_AX);
    u32*   BuHi   = (u32*)(sm + OF_BU);
    u32*   BuLo   = (u32*)(sm + OF_BL);
    float* bounce = (float*)(sm + OF_BU);       // alias (post-MMA)

    const int tid = threadIdx.x, w = tid >> 5, lane = tid & 31;
    const int m = blockIdx.x & 7, s = blockIdx.x >> 3;
    const int gr = lane >> 2, tq = lane & 3;
    const int mg = w & 3, ns = w >> 2;          // warp = m32 x n16 tile
    const int r0 = mg * 32, nb0 = ns * 16;

    loadA(0, m, tid, sm);
    if (tid < 128)
        sbias[tid] = enc_b[((tid >> 5) << 8) + (m << 5) + (tid & 31)];
    copyPlane(sb, OF_BU, g_hHi[0] + (size_t)(s * 8) * 64 * 128, tid);
    copyPlane(sb, OF_BL, g_hLo[0] + (size_t)(s * 8) * 64 * 128, tid);
    copyX(sb, OF_BX0, g_xT + (size_t)(0 * 128 + s * 8) * 1024, tid);
    CPA_COMMIT(); CPA_WAIT0();
    __syncthreads();

    float cst[8][4];
    #pragma unroll
    for (int q = 0; q < 8; ++q)
        #pragma unroll
        for (int j = 0; j < 4; ++j) cst[q][j] = 0.f;

    int pp = 0;

    for (int t = 0; t < 72; ++t) {
        #pragma unroll 1
        for (int q = 0; q < 8; ++q) {
            const int sq = s * 8 + q;
            const int bxOff = (q & 1) ? OF_BX1 : OF_BX0;

            float acc[2][2][4];
            #pragma unroll
            for (int mi = 0; mi < 2; ++mi)
                #pragma unroll
                for (int nt = 0; nt < 2; ++nt)
                    #pragma unroll
                    for (int j = 0; j < 4; ++j) acc[mi][nt][j] = 0.f;

            if (t < 48) {
                u32* Bx = (u32*)(sm + bxOff);
                uint2 AH[4], AL[4], BH[2], BL[2];
                #pragma unroll
                for (int rr = 0; rr < 4; ++rr) {
                    AH[rr] = *(const uint2*)&Ax[(r0 + 8 * rr + gr) * 20 + tq * 2];
                    AL[rr] = *(const uint2*)&Ax[(r0 + 8 * rr + gr) * 20 + 8 + tq * 2];
                }
                #pragma unroll
                for (int nt = 0; nt < 2; ++nt) {
                    BH[nt] = *(const uint2*)&Bx[(nb0 + nt * 8 + gr) * 20 + tq * 2];
                    BL[nt] = *(const uint2*)&Bx[(nb0 + nt * 8 + gr) * 20 + 8 + tq * 2];
                }
                #pragma unroll
                for (int mi = 0; mi < 2; ++mi)
                    #pragma unroll
                    for (int nt = 0; nt < 2; ++nt) {
                        mma16816(acc[mi][nt], AH[2*mi].x, AH[2*mi+1].x,
                                 AH[2*mi].y, AH[2*mi+1].y, BH[nt].x, BH[nt].y);
                        mma16816(acc[mi][nt], AH[2*mi].x, AH[2*mi+1].x,
                                 AH[2*mi].y, AH[2*mi+1].y, BL[nt].x, BL[nt].y);
                        mma16816(acc[mi][nt], AL[2*mi].x, AL[2*mi+1].x,
                                 AL[2*mi].y, AL[2*mi+1].y, BH[nt].x, BH[nt].y);
                    }
            }

            // ---- Whh MMAs: software-pipelined ks loop ----
            {
                const u32* ah = AuHi + (r0 + gr) * STR + tq * 2;
                const u32* al = AuLo + (r0 + gr) * STR + tq * 2;
                const u32* bh = BuHi + (nb0 + gr) * STR + tq * 2;
                const u32* bl = BuLo + (nb0 + gr) * STR + tq * 2;
                uint2 AH[2][4], AL[2][4], BH[2][2], BL[2];
                #pragma unroll
                for (int rr = 0; rr < 4; ++rr) {
                    AH[0][rr] = *(const uint2*)(ah + rr * 8 * STR);
                    AL[0][rr] = *(const uint2*)(al + rr * 8 * STR);
                }
                #pragma unroll
                for (int nt = 0; nt < 2; ++nt)
                    BH[0][nt] = *(const uint2*)(bh + nt * 8 * STR);
                #pragma unroll
                for (int ks = 0; ks < 16; ++ks) {
                    const int cur = ks & 1, nx = cur ^ 1;
                    // just-in-time B-lo for this ks (used from MMA #5)
                    #pragma unroll
                    for (int nt = 0; nt < 2; ++nt)
                        BL[nt] = *(const uint2*)(bl + nt * 8 * STR + ks * 8);
                    // prefetch ks+1 fragments (A-hi, A-lo, B-hi)
                    if (ks < 15) {
                        #pragma unroll
                        for (int rr = 0; rr < 4; ++rr) {
                            AH[nx][rr] = *(const uint2*)(ah + rr * 8 * STR + (ks + 1) * 8);
                            AL[nx][rr] = *(const uint2*)(al + rr * 8 * STR + (ks + 1) * 8);
                        }
                        #pragma unroll
                        for (int nt = 0; nt < 2; ++nt)
                            BH[nx][nt] = *(const uint2*)(bh + nt * 8 * STR + (ks + 1) * 8);
                    }
                    // P1: Whi x h_hi
                    #pragma unroll
                    for (int mi = 0; mi < 2; ++mi)
                        #pragma unroll
                        for (int nt = 0; nt < 2; ++nt)
                            mma16816(acc[mi][nt],
                                     AH[cur][2*mi].x, AH[cur][2*mi+1].x,
                                     AH[cur][2*mi].y, AH[cur][2*mi+1].y,
                                     BH[cur][nt].x, BH[cur][nt].y);
                    // P2: Whi x h_lo
                    #pragma unroll
                    for (int mi = 0; mi < 2; ++mi)
                        #pragma unroll
                        for (int nt = 0; nt < 2; ++nt)
                            mma16816(acc[mi][nt],
                                     AH[cur][2*mi].x, AH[cur][2*mi+1].x,
                                     AH[cur][2*mi].y, AH[cur][2*mi+1].y,
                                     BL[nt].x, BL[nt].y);
                    // P3: Wlo x h_hi
                    #pragma unroll
                    for (int mi = 0; mi < 2; ++mi)
                        #pragma unroll
                        for (int nt = 0; nt < 2; ++nt)
                            mma16816(acc[mi][nt],
                                     AL[cur][2*mi].x, AL[cur][2*mi+1].x,
                                     AL[cur][2*mi].y, AL[cur][2*mi+1].y,
                                     BH[cur][nt].x, BH[cur][nt].y);
                }
            }
            __syncthreads();        // B reads done

            // prefetch next chunk's B-lo (+x) under bounce/update (BuLo free)
            if (q < 7) {
                copyPlane(sb, OF_BL,
                          g_hLo[pp] + (size_t)(sq + 1) * 64 * 128, tid);
                if (t < 48)
                    copyX(sb, (q & 1) ? OF_BX0 : OF_BX1,
                          g_xT + (size_t)(t * 128 + sq + 1) * 1024, tid);
                CPA_COMMIT();
            }

            // ---- bounce write (+bias) into BuHi region ----
            #pragma unroll
            for (int mi = 0; mi < 2; ++mi) {
                int rm = r0 + 16 * mi;
                float b0 = sbias[rm + gr], b1 = sbias[rm + 8 + gr];
                #pragma unroll
                for (int nt = 0; nt < 2; ++nt) {
                    int n = nb0 + nt * 8 + 2 * tq;
                    bounce[(rm + gr) * 65 + n]         = acc[mi][nt][0] + b0;
                    bounce[(rm + gr) * 65 + n + 1]     = acc[mi][nt][1] + b0;
                    bounce[(rm + 8 + gr) * 65 + n]     = acc[mi][nt][2] + b1;
                    bounce[(rm + 8 + gr) * 65 + n + 1] = acc[mi][nt][3] + b1;
                }
            }
            __syncthreads();

            // ---- LSTM cell update + split/scol'd h store ----
            {
                int nn = tid >> 3, kq = tid & 7;
                float hval[4];
                #pragma unroll
                for (int j = 0; j < 4; ++j) {
                    int kk = kq * 4 + j;
                    float gi = bounce[kk * 65 + nn];
                    float gf = bounce[(32 + kk) * 65 + nn];
                    float gg = bounce[(64 + kk) * 65 + nn];
                    float go = bounce[(96 + kk) * 65 + nn];
                    float cn = sigf(gf) * cst[q][j] + sigf(gi) * tanh_(gg);
                    cst[q][j] = cn;
                    hval[j] = sigf(go) * tanh_(cn);
                }
                u16 h0, l0, h1, l1, h2, l2, h3, l3;
                split16(hval[0], h0, l0); split16(hval[1], h1, l1);
                split16(hval[2], h2, l2); split16(hval[3], h3, l3);
                size_t row = (size_t)(sq * 64 + nn) * 128;
                int c0 = m * 16 + scol(2 * kq);
                int c1 = m * 16 + scol(2 * kq + 1);
                g_hHi[pp ^ 1][row + c0] = (u32)h0 | ((u32)h1 << 16);
                g_hHi[pp ^ 1][row + c1] = (u32)h2 | ((u32)h3 << 16);
                g_hLo[pp ^ 1][row + c0] = (u32)l0 | ((u32)l1 << 16);
                g_hLo[pp ^ 1][row + c1] = (u32)l2 | ((u32)l3 << 16);
            }
            __syncthreads();        // bounce reads done -> BuHi free

            if (q < 7) {
                copyPlane(sb, OF_BU,
                          g_hHi[pp] + (size_t)(sq + 1) * 64 * 128, tid);
                CPA_COMMIT();
            }
            CPA_WAIT0();
            __syncthreads();
        }

        // ---- slice barrier (8 peer CTAs) ----
        if (tid == 0) {
            __threadfence();
            atomicAdd(&g_ctr[s * 72 + t], 1);
            int v;
            do {
                asm volatile("ld.global.acquire.gpu.b32 %0, [%1];"
                             : "=r"(v) : "l"(&g_ctr[s * 72 + t]));
            } while (v < 8);
        }
        __syncthreads();
        pp ^= 1;

        // ---- decoder dense epilogue ----
        if (t >= 48) {
            int td = t - 48;
            const size_t hb = (size_t)(s * 8 + m) * 64 * 128;
            copyPlane(sb, OF_BU, g_hHi[pp] + hb, tid);
            copyPlane(sb, OF_BL, g_hLo[pp] + hb, tid);
            float* wstage = (float*)(sm + OF_AX);
            {
                float4 wv = *(const float4*)(g_dWp + td * 2048 + tid * 4);
                int o = tid >> 6, k4 = tid & 63;
                *(float4*)&wstage[o * 260 + k4 * 4] = wv;
            }
            CPA_COMMIT(); CPA_WAIT0();
            __syncthreads();
            int n_l = tid >> 3, o2 = tid & 7;
            const u32* hh = BuHi + n_l * STR;
            const u32* hl = BuLo + n_l * STR;
            const float2* wr = (const float2*)&wstage[o2 * 260];
            float a = __ldg(db + td * 8 + o2);
            #pragma unroll 8
            for (int pi = 0; pi < 128; ++pi) {
                float2 ph = bf2f(hh[pi]), pl = bf2f(hl[pi]);
                float2 wv = wr[pi];
                a = fmaf(ph.x + pl.x, wv.x, a);
                a = fmaf(ph.y + pl.y, wv.y, a);
            }
            out[((size_t)(s * 512 + m * 64 + n_l) * 8 + o2) * 24 + td] = a;
            __syncthreads();
        }

        if (t == 47) {
            loadA(1, m, tid, sm);
            if (tid < 128)
                sbias[tid] = dec_b[((tid >> 5) << 8) + (m << 5) + (tid & 31)];
            #pragma unroll
            for (int q = 0; q < 8; ++q)
                #pragma unroll
                for (int j = 0; j < 4; ++j) cst[q][j] = 0.f;
        }

        if (t < 71) {       // copies for (t+1, q=0)
            copyPlane(sb, OF_BU, g_hHi[pp] + (size_t)(s * 8) * 64 * 128, tid);
            copyPlane(sb, OF_BL, g_hLo[pp] + (size_t)(s * 8) * 64 * 128, tid);
            if (t < 47)
                copyX(sb, OF_BX0,
                      g_xT + (size_t)((t + 1) * 128 + s * 8) * 1024, tid);
            CPA_COMMIT(); CPA_WAIT0();
        }
        __syncthreads();
    }
}

// ---------------------------------------------------------------------------
extern "C" void kernel_launch(void* const* d_in, const int* in_sizes, int n_in,
                              void* d_out, int out_size)
{
    (void)in_sizes; (void)n_in; (void)out_size;
    const float* x       = (const float*)d_in[0];
    const float* enc_Wih = (const float*)d_in[1];
    const float* enc_Whh = (const float*)d_in[2];
    const float* enc_b   = (const float*)d_in[3];
    const float* dec_Whh = (const float*)d_in[4];
    const float* dec_b   = (const float*)d_in[5];
    const float* dense_W = (const float*)d_in[6];
    const float* dense_b = (const float*)d_in[7];
    float* out = (float*)d_out;

    cudaFuncSetAttribute(lstm_mma,
                         cudaFuncAttributeMaxDynamicSharedMemorySize, SMEM_BYTES);

    prep_kernel<<<2048, 256>>>(x, enc_Wih, enc_Whh, dec_Whh, dense_W);
    lstm_mma<<<128, 512, SMEM_BYTES>>>(enc_b, dec_b, dense_b, out);
}

// round 16
// speedup vs baseline: 1.2207x; 1.2207x over previous
#include <cuda_runtime.h>
#include <cuda_bf16.h>

// Seq2seq LSTM via mma.sync.m16n8k16.bf16, split-bf16 (hi+lo, 3 products),
// fp32 accumulation. 128 persistent CTAs = 16 slices x 8 M-groups.
// R16 = R14 + gate-interleaved A-row permutation -> LSTM cell update fully
// in registers (no bounce SMEM, 2 barriers/chunk instead of 4), h pair
// packing via shfl_xor+prmt, all next-chunk copies overlap the update.

typedef unsigned int u32;
typedef unsigned short u16;

#define HID 256
#define NB  8192
#define PLANE (NB * 128)           // u32 pairs per h plane
#define STR 136                    // u32 row stride (8 mod 32: conflict-free)

__device__ __align__(16) u32 g_Wh[2][1024][128];   // Whh hi pairs
__device__ __align__(16) u32 g_Wl[2][1024][128];   // Whh lo pairs
__device__ __align__(16) u32 g_Wxh[1024][8];       // Wih hi pairs
__device__ __align__(16) u32 g_Wxl[1024][8];       // Wih lo pairs
__device__ __align__(16) u32 g_xT[48 * 128 * 64 * 16]; // x tile images
__device__ __align__(16) u32 g_hHi[2][PLANE];      // h hi pairs, scol'd
__device__ __align__(16) u32 g_hLo[2][PLANE];      // h lo pairs, scol'd
__device__ __align__(16) float g_dWp[24 * 8 * 256];    // dense W, k-permuted
__device__ int g_ctr[16 * 72];

// ---- helpers ---------------------------------------------------------------
__device__ __forceinline__ u32 smem_u32(const void* p) {
    u32 a;
    asm("{ .reg .u64 t; cvta.to.shared.u64 t, %1; cvt.u32.u64 %0, t; }"
        : "=r"(a) : "l"(p));
    return a;
}
__device__ __forceinline__ void cpa16(u32 dst, const void* src) {
    asm volatile("cp.async.cg.shared.global [%0], [%1], 16;"
                 :: "r"(dst), "l"(src));
}
#define CPA_COMMIT() asm volatile("cp.async.commit_group;" ::: "memory")
#define CPA_WAIT0()  asm volatile("cp.async.wait_group 0;" ::: "memory")

__device__ __forceinline__ u32 prmt(u32 a, u32 b, u32 s) {
    u32 d;
    asm("prmt.b32 %0,%1,%2,%3;" : "=r"(d) : "r"(a), "r"(b), "r"(s));
    return d;
}
__device__ __forceinline__ void mma16816(float* d, u32 a0, u32 a1, u32 a2,
                                         u32 a3, u32 b0, u32 b1) {
    asm volatile(
        "mma.sync.aligned.m16n8k16.row.col.f32.bf16.bf16.f32 "
        "{%0,%1,%2,%3}, {%4,%5,%6,%7}, {%8,%9}, {%0,%1,%2,%3};"
        : "+f"(d[0]), "+f"(d[1]), "+f"(d[2]), "+f"(d[3])
        : "r"(a0), "r"(a1), "r"(a2), "r"(a3), "r"(b0), "r"(b1));
}
__device__ __forceinline__ float sigf(float x) {
    return __fdividef(1.0f, 1.0f + __expf(-x));
}
__device__ __forceinline__ float tanh_(float x) {
    return 1.0f - __fdividef(2.0f, __expf(2.0f * x) + 1.0f);
}
__device__ __forceinline__ void split16(float v, u16& h, u16& l) {
    __nv_bfloat16 hb = __float2bfloat16(v);
    __nv_bfloat16 lb = __float2bfloat16(v - __bfloat162float(hb));
    h = *(u16*)&hb; l = *(u16*)&lb;
}
__device__ __forceinline__ u32 packsplit(float v) {
    u16 h, l; split16(v, h, l);
    return (u32)h | ((u32)l << 16);
}
__device__ __forceinline__ float2 bf2f(u32 v) {
    return __bfloat1622float2(*(__nv_bfloat162*)&v);
}
// pair j -> storage col (scol): (b0,b1) of a fragment = one LDS.64
__device__ __forceinline__ int scol(int j) {
    return (j & ~7) + ((j & 3) << 1) + ((j >> 2) & 1);
}
// gate-interleaved A-tile row r -> global gate row G (CTA m-group m)
__device__ __forceinline__ int rowG(int r, int m) {
    return (((r >> 3) & 3) << 8) + (m << 5) + (((r >> 5) << 3) | (r & 7));
}

// ---- SMEM byte layout -------------------------------------------------------
#define OF_AU   1024            // Whi tile 128xSTR u32 = 69632
#define OF_AL   70656           // Wlo tile 69632
#define OF_AX   140288          // Wx tile 128x20 u32 = 10240 (alias: dense W)
#define OF_BX0  150528          // x tile ping 64x20 u32 = 5120
#define OF_BX1  155648          // x tile pong 5120
#define OF_BU   160768          // h_hi tile 64xSTR = 34816 (alias: dense h)
#define OF_BL   195584          // h_lo tile 34816
#define SMEM_BYTES 230400

// ---------------------------------------------------------------------------
__global__ void prep_kernel(const float* __restrict__ x,
                            const float* __restrict__ Wih,
                            const float* __restrict__ Whhe,
                            const float* __restrict__ Whhd,
                            const float* __restrict__ dW)
{
    const int S1 = 2 * 1024 * 128;
    const int S2 = S1 + 1024 * 8;
    const int S3 = S2 + 2 * PLANE;
    const int S4 = S3 + 16 * 72;
    const int S5 = S4 + 48 * 128 * 64 * 8;
    const int S6 = S5 + 24 * 8 * 256;
    for (int i = blockIdx.x * blockDim.x + threadIdx.x; i < S6;
         i += gridDim.x * blockDim.x) {
        if (i < S1) {
            int which = i >> 17, j = i & 131071;
            int G = j >> 7, col = j & 127;
            const float* W = which ? Whhd : Whhe;
            u16 ha, la, hb, lb;
            split16(W[G * HID + 2 * col], ha, la);
            split16(W[G * HID + 2 * col + 1], hb, lb);
            g_Wh[which][G][col] = (u32)ha | ((u32)hb << 16);
            g_Wl[which][G][col] = (u32)la | ((u32)lb << 16);
        } else if (i < S2) {
            int j = i - S1, G = j >> 3, cp = j & 7;
            u16 ha, la, hb, lb;
            split16(Wih[G * 16 + 2 * cp], ha, la);
            split16(Wih[G * 16 + 2 * cp + 1], hb, lb);
            g_Wxh[G][cp] = (u32)ha | ((u32)hb << 16);
            g_Wxl[G][cp] = (u32)la | ((u32)lb << 16);
        } else if (i < S3) {
            int j = i - S2;
            if (j < PLANE) g_hHi[0][j] = 0; else g_hLo[0][j - PLANE] = 0;
        } else if (i < S4) {
            g_ctr[i - S3] = 0;
        } else if (i < S5) {
            int j = i - S4;
            int cp = j & 7, n = (j >> 3) & 63, sq = (j >> 9) & 127, t = j >> 16;
            u16 ha, la, hb, lb;
            int ng = sq * 64 + n;
            split16(x[(ng * 16 + 2 * cp) * 48 + t], ha, la);
            split16(x[(ng * 16 + 2 * cp + 1) * 48 + t], hb, lb);
            int sc = ((cp & 3) << 1) + (cp >> 2);      // scol within 8-group
            u32* dst = g_xT + ((t * 128 + sq) * 64 + n) * 16;
            dst[sc]     = (u32)ha | ((u32)hb << 16);
            dst[8 + sc] = (u32)la | ((u32)lb << 16);
        } else {
            int j = i - S5;
            int k = j & 255, o = (j >> 8) & 7, td = j >> 11;
            g_dWp[td * 2048 + o * 256 + 2 * scol(k >> 1) + (k & 1)] =
                dW[td * 2048 + o * 256 + k];
        }
    }
}

// ---------------------------------------------------------------------------
__device__ __forceinline__ void loadA(int which, int m, int tid, char* sm)
{
    u32* AuHi = (u32*)(sm + OF_AU);
    u32* AuLo = (u32*)(sm + OF_AL);
    u32* Ax   = (u32*)(sm + OF_AX);
    for (int i = tid; i < 128 * 128; i += 512) {
        int r = i >> 7, j = i & 127;
        int G = rowG(r, m);
        int col = scol(j);
        AuHi[r * STR + col] = g_Wh[which][G][j];
        AuLo[r * STR + col] = g_Wl[which][G][j];
    }
    if (which == 0) {
        for (int i = tid; i < 128 * 8; i += 512) {
            int r = i >> 3, j = i & 7;
            int G = rowG(r, m);
            int col = ((j & 3) << 1) + (j >> 2);
            Ax[r * 20 + col]     = g_Wxh[G][j];
            Ax[r * 20 + 8 + col] = g_Wxl[G][j];
        }
    }
}

// cp.async one 32KB h plane tile (64 rows x 128 u32 pairs) into padded tile.
__device__ __forceinline__ void copyPlane(u32 sb, int dstOff,
                                          const u32* __restrict__ src, int tid)
{
    int n = tid >> 3;
    #pragma unroll
    for (int it = 0; it < 4; ++it) {
        int c = (tid & 7) + it * 8;
        cpa16(sb + dstOff + (n * STR + c * 4) * 4, src + n * 128 + c * 4);
    }
}
__device__ __forceinline__ void copyX(u32 sb, int dstOff,
                                      const u32* __restrict__ src, int tid)
{
    if (tid < 256) {
        int n = tid >> 2, c4 = tid & 3;
        cpa16(sb + dstOff + (n * 20 + c4 * 4) * 4, src + n * 16 + c4 * 4);
    }
}

// ---------------------------------------------------------------------------
__global__ void __launch_bounds__(512, 1)
lstm_mma(const float* __restrict__ enc_b, const float* __restrict__ dec_b,
         const float* __restrict__ db, float* __restrict__ out)
{
    extern __shared__ char sm[];
    const u32 sb = smem_u32(sm);
    u32*   AuHi   = (u32*)(sm + OF_AU);
    u32*   AuLo   = (u32*)(sm + OF_AL);
    u32*   Ax     = (u32*)(sm + OF_AX);
    u32*   BuHi   = (u32*)(sm + OF_BU);
    u32*   BuLo   = (u32*)(sm + OF_BL);

    const int tid = threadIdx.x, w = tid >> 5, lane = tid & 31;
    const int m = blockIdx.x & 7, s = blockIdx.x >> 3;
    const int gr = lane >> 2, tq = lane & 3;
    const int mg = w & 3, ns = w >> 2;          // warp = m32 x n16 tile
    const int r0 = mg * 32, nb0 = ns * 16;
    const int kkg = m * 32 + mg * 8 + gr;       // this thread's global k row

    loadA(0, m, tid, sm);
    float bi = enc_b[kkg],       bf = enc_b[256 + kkg];
    float bg = enc_b[512 + kkg], bo = enc_b[768 + kkg];
    copyPlane(sb, OF_BU, g_hHi[0] + (size_t)(s * 8) * 64 * 128, tid);
    copyPlane(sb, OF_BL, g_hLo[0] + (size_t)(s * 8) * 64 * 128, tid);
    copyX(sb, OF_BX0, g_xT + (size_t)(0 * 128 + s * 8) * 1024, tid);
    CPA_COMMIT(); CPA_WAIT0();
    __syncthreads();

    float cst[8][4];
    #pragma unroll
    for (int q = 0; q < 8; ++q)
        #pragma unroll
        for (int j = 0; j < 4; ++j) cst[q][j] = 0.f;

    // h store constants (cell (kk, n): pair partner = lane^4)
    const int hcol  = m * 16 + scol(mg * 4 + (gr >> 1));
    const bool evenk = (gr & 1) == 0;
    const u32 psel  = evenk ? 0x5410u : 0x7632u;

    int pp = 0;

    for (int t = 0; t < 72; ++t) {
        #pragma unroll 1
        for (int q = 0; q < 8; ++q) {
            const int sq = s * 8 + q;
            const int bxOff = (q & 1) ? OF_BX1 : OF_BX0;

            float acc[2][2][4];
            #pragma unroll
            for (int mi = 0; mi < 2; ++mi)
                #pragma unroll
                for (int nt = 0; nt < 2; ++nt)
                    #pragma unroll
                    for (int j = 0; j < 4; ++j) acc[mi][nt][j] = 0.f;

            if (t < 48) {
                u32* Bx = (u32*)(sm + bxOff);
                uint2 AH[4], AL[4], BH[2], BL[2];
                #pragma unroll
                for (int rr = 0; rr < 4; ++rr) {
                    AH[rr] = *(const uint2*)&Ax[(r0 + 8 * rr + gr) * 20 + tq * 2];
                    AL[rr] = *(const uint2*)&Ax[(r0 + 8 * rr + gr) * 20 + 8 + tq * 2];
                }
                #pragma unroll
                for (int nt = 0; nt < 2; ++nt) {
                    BH[nt] = *(const uint2*)&Bx[(nb0 + nt * 8 + gr) * 20 + tq * 2];
                    BL[nt] = *(const uint2*)&Bx[(nb0 + nt * 8 + gr) * 20 + 8 + tq * 2];
                }
                #pragma unroll
                for (int mi = 0; mi < 2; ++mi)
                    #pragma unroll
                    for (int nt = 0; nt < 2; ++nt) {
                        mma16816(acc[mi][nt], AH[2*mi].x, AH[2*mi+1].x,
                                 AH[2*mi].y, AH[2*mi+1].y, BH[nt].x, BH[nt].y);
                        mma16816(acc[mi][nt], AH[2*mi].x, AH[2*mi+1].x,
                                 AH[2*mi].y, AH[2*mi+1].y, BL[nt].x, BL[nt].y);
                        mma16816(acc[mi][nt], AL[2*mi].x, AL[2*mi+1].x,
                                 AL[2*mi].y, AL[2*mi+1].y, BH[nt].x, BH[nt].y);
                    }
            }
            {
                const u32* ah = AuHi + (r0 + gr) * STR + tq * 2;
                const u32* al = AuLo + (r0 + gr) * STR + tq * 2;
                const u32* bh = BuHi + (nb0 + gr) * STR + tq * 2;
                const u32* bl = BuLo + (nb0 + gr) * STR + tq * 2;
                #pragma unroll 2
                for (int ks = 0; ks < 16; ++ks) {
                    uint2 AH[4], AL[4], BH[2], BL[2];
                    #pragma unroll
                    for (int rr = 0; rr < 4; ++rr) {
                        AH[rr] = *(const uint2*)(ah + rr * 8 * STR + ks * 8);
                        AL[rr] = *(const uint2*)(al + rr * 8 * STR + ks * 8);
                    }
                    #pragma unroll
                    for (int nt = 0; nt < 2; ++nt) {
                        BH[nt] = *(const uint2*)(bh + nt * 8 * STR + ks * 8);
                        BL[nt] = *(const uint2*)(bl + nt * 8 * STR + ks * 8);
                    }
                    #pragma unroll
                    for (int mi = 0; mi < 2; ++mi)
                        #pragma unroll
                        for (int nt = 0; nt < 2; ++nt) {
                            mma16816(acc[mi][nt], AH[2*mi].x, AH[2*mi+1].x,
                                     AH[2*mi].y, AH[2*mi+1].y, BH[nt].x, BH[nt].y);
                            mma16816(acc[mi][nt], AH[2*mi].x, AH[2*mi+1].x,
                                     AH[2*mi].y, AH[2*mi+1].y, BL[nt].x, BL[nt].y);
                            mma16816(acc[mi][nt], AL[2*mi].x, AL[2*mi+1].x,
                                     AL[2*mi].y, AL[2*mi+1].y, BH[nt].x, BH[nt].y);
                        }
                }
            }
            __syncthreads();        // B reads done -> tiles may be overwritten

            // prefetch next chunk's B tiles + x under the register update
            if (q < 7) {
                copyPlane(sb, OF_BU,
                          g_hHi[pp] + (size_t)(sq + 1) * 64 * 128, tid);
                copyPlane(sb, OF_BL,
                          g_hLo[pp] + (size_t)(sq + 1) * 64 * 128, tid);
                if (t < 48)
                    copyX(sb, (q & 1) ? OF_BX0 : OF_BX1,
                          g_xT + (size_t)(t * 128 + sq + 1) * 1024, tid);
                CPA_COMMIT();
            }

            // ---- LSTM cell update fully in registers ----
            // acc[0][nt][0,1]=i, acc[0][nt][2,3]=f,
            // acc[1][nt][0,1]=g, acc[1][nt][2,3]=o   (row permutation rowG)
            {
                u32 ps[4];
                #pragma unroll
                for (int nt = 0; nt < 2; ++nt)
                    #pragma unroll
                    for (int j = 0; j < 2; ++j) {
                        int ci = nt * 2 + j;
                        float gi = acc[0][nt][j]     + bi;
                        float gf = acc[0][nt][2 + j] + bf;
                        float gg = acc[1][nt][j]     + bg;
                        float go = acc[1][nt][2 + j] + bo;
                        float cn = sigf(gf) * cst[q][ci] + sigf(gi) * tanh_(gg);
                        cst[q][ci] = cn;
                        ps[ci] = packsplit(sigf(go) * tanh_(cn));
                    }
                u32* plane = (evenk ? g_hHi : g_hLo)[pp ^ 1];
                #pragma unroll
                for (int ci = 0; ci < 4; ++ci) {
                    u32 po = __shfl_xor_sync(0xFFFFFFFFu, ps[ci], 4);
                    u32 a  = evenk ? ps[ci] : po;
                    u32 b  = evenk ? po : ps[ci];
                    u32 word = prmt(a, b, psel);
                    int n = nb0 + (ci >> 1) * 8 + 2 * tq + (ci & 1);
                    plane[(size_t)(sq * 64 + n) * 128 + hcol] = word;
                }
            }

            CPA_WAIT0();
            __syncthreads();
        }

        // ---- slice barrier (8 peer CTAs) ----
        if (tid == 0) {
            __threadfence();
            atomicAdd(&g_ctr[s * 72 + t], 1);
            int v;
            do {
                asm volatile("ld.global.acquire.gpu.b32 %0, [%1];"
                             : "=r"(v) : "l"(&g_ctr[s * 72 + t]));
            } while (v < 8);
        }
        __syncthreads();
        pp ^= 1;

        // ---- decoder dense epilogue ----
        if (t >= 48) {
            int td = t - 48;
            const size_t hb = (size_t)(s * 8 + m) * 64 * 128;
            copyPlane(sb, OF_BU, g_hHi[pp] + hb, tid);
            copyPlane(sb, OF_BL, g_hLo[pp] + hb, tid);
            float* wstage = (float*)(sm + OF_AX);
            {
                float4 wv = *(const float4*)(g_dWp + td * 2048 + tid * 4);
                int o = tid >> 6, k4 = tid & 63;
                *(float4*)&wstage[o * 260 + k4 * 4] = wv;
            }
            CPA_COMMIT(); CPA_WAIT0();
            __syncthreads();
            int n_l = tid >> 3, o2 = tid & 7;
            const u32* hh = BuHi + n_l * STR;
            const u32* hl = BuLo + n_l * STR;
            const float2* wr = (const float2*)&wstage[o2 * 260];
            float a = __ldg(db + td * 8 + o2);
            #pragma unroll 8
            for (int pi = 0; pi < 128; ++pi) {
                float2 ph = bf2f(hh[pi]), pl = bf2f(hl[pi]);
                float2 wv = wr[pi];
                a = fmaf(ph.x + pl.x, wv.x, a);
                a = fmaf(ph.y + pl.y, wv.y, a);
            }
            out[((size_t)(s * 512 + m * 64 + n_l) * 8 + o2) * 24 + td] = a;
            __syncthreads();
        }

        if (t == 47) {
            loadA(1, m, tid, sm);
            bi = dec_b[kkg];       bf = dec_b[256 + kkg];
            bg = dec_b[512 + kkg]; bo = dec_b[768 + kkg];
            #pragma unroll
            for (int q = 0; q < 8; ++q)
                #pragma unroll
                for (int j = 0; j < 4; ++j) cst[q][j] = 0.f;
        }

        if (t < 71) {       // copies for (t+1, q=0)
            copyPlane(sb, OF_BU, g_hHi[pp] + (size_t)(s * 8) * 64 * 128, tid);
            copyPlane(sb, OF_BL, g_hLo[pp] + (size_t)(s * 8) * 64 * 128, tid);
            if (t < 47)
                copyX(sb, OF_BX0,
                      g_xT + (size_t)((t + 1) * 128 + s * 8) * 1024, tid);
            CPA_COMMIT(); CPA_WAIT0();
        }
        __syncthreads();
    }
}

// ---------------------------------------------------------------------------
extern "C" void kernel_launch(void* const* d_in, const int* in_sizes, int n_in,
                              void* d_out, int out_size)
{
    (void)in_sizes; (void)n_in; (void)out_size;
    const float* x       = (const float*)d_in[0];
    const float* enc_Wih = (const float*)d_in[1];
    const float* enc_Whh = (const float*)d_in[2];
    const float* enc_b   = (const float*)d_in[3];
    const float* dec_Whh = (const float*)d_in[4];
    const float* dec_b   = (const float*)d_in[5];
    const float* dense_W = (const float*)d_in[6];
    const float* dense_b = (const float*)d_in[7];
    float* out = (float*)d_out;

    cudaFuncSetAttribute(lstm_mma,
                         cudaFuncAttributeMaxDynamicSharedMemorySize, SMEM_BYTES);

    prep_kernel<<<2048, 256>>>(x, enc_Wih, enc_Whh, dec_Whh, dense_W);
    lstm_mma<<<128, 512, SMEM_BYTES>>>(enc_b, dec_b, dense_b, out);
}

// round 17
// speedup vs baseline: 1.2268x; 1.0050x over previous
#include <cuda_runtime.h>
#include <cuda_bf16.h>

// Seq2seq LSTM via mma.sync.m16n8k16.bf16, split-bf16 (hi+lo, 3 products),
// fp32 accumulation. 128 persistent CTAs = 16 slices x 8 M-groups.
// R17 = R16 with m32 x n32 warp tiles on 8 MMA warps (0.67 LDS.64/MMA);
// warps 8-15 are copy warps (cp.async overlapped with the register update).

typedef unsigned int u32;
typedef unsigned short u16;

#define HID 256
#define NB  8192
#define PLANE (NB * 128)           // u32 pairs per h plane
#define STR 136                    // u32 row stride (8 mod 32: conflict-free)

__device__ __align__(16) u32 g_Wh[2][1024][128];   // Whh hi pairs
__device__ __align__(16) u32 g_Wl[2][1024][128];   // Whh lo pairs
__device__ __align__(16) u32 g_Wxh[1024][8];       // Wih hi pairs
__device__ __align__(16) u32 g_Wxl[1024][8];       // Wih lo pairs
__device__ __align__(16) u32 g_xT[48 * 128 * 64 * 16]; // x tile images
__device__ __align__(16) u32 g_hHi[2][PLANE];      // h hi pairs, scol'd
__device__ __align__(16) u32 g_hLo[2][PLANE];      // h lo pairs, scol'd
__device__ __align__(16) float g_dWp[24 * 8 * 256];    // dense W, k-permuted
__device__ int g_ctr[16 * 72];

// ---- helpers ---------------------------------------------------------------
__device__ __forceinline__ u32 smem_u32(const void* p) {
    u32 a;
    asm("{ .reg .u64 t; cvta.to.shared.u64 t, %1; cvt.u32.u64 %0, t; }"
        : "=r"(a) : "l"(p));
    return a;
}
__device__ __forceinline__ void cpa16(u32 dst, const void* src) {
    asm volatile("cp.async.cg.shared.global [%0], [%1], 16;"
                 :: "r"(dst), "l"(src));
}
#define CPA_COMMIT() asm volatile("cp.async.commit_group;" ::: "memory")
#define CPA_WAIT0()  asm volatile("cp.async.wait_group 0;" ::: "memory")

__device__ __forceinline__ u32 prmt(u32 a, u32 b, u32 s) {
    u32 d;
    asm("prmt.b32 %0,%1,%2,%3;" : "=r"(d) : "r"(a), "r"(b), "r"(s));
    return d;
}
__device__ __forceinline__ void mma16816(float* d, u32 a0, u32 a1, u32 a2,
                                         u32 a3, u32 b0, u32 b1) {
    asm volatile(
        "mma.sync.aligned.m16n8k16.row.col.f32.bf16.bf16.f32 "
        "{%0,%1,%2,%3}, {%4,%5,%6,%7}, {%8,%9}, {%0,%1,%2,%3};"
        : "+f"(d[0]), "+f"(d[1]), "+f"(d[2]), "+f"(d[3])
        : "r"(a0), "r"(a1), "r"(a2), "r"(a3), "r"(b0), "r"(b1));
}
__device__ __forceinline__ float sigf(float x) {
    return __fdividef(1.0f, 1.0f + __expf(-x));
}
__device__ __forceinline__ float tanh_(float x) {
    return 1.0f - __fdividef(2.0f, __expf(2.0f * x) + 1.0f);
}
__device__ __forceinline__ void split16(float v, u16& h, u16& l) {
    __nv_bfloat16 hb = __float2bfloat16(v);
    __nv_bfloat16 lb = __float2bfloat16(v - __bfloat162float(hb));
    h = *(u16*)&hb; l = *(u16*)&lb;
}
__device__ __forceinline__ u32 packsplit(float v) {
    u16 h, l; split16(v, h, l);
    return (u32)h | ((u32)l << 16);
}
__device__ __forceinline__ float2 bf2f(u32 v) {
    return __bfloat1622float2(*(__nv_bfloat162*)&v);
}
// pair j -> storage col (scol): (b0,b1) of a fragment = one LDS.64
__device__ __forceinline__ int scol(int j) {
    return (j & ~7) + ((j & 3) << 1) + ((j >> 2) & 1);
}
// gate-interleaved A-tile row r -> global gate row G (CTA m-group m)
__device__ __forceinline__ int rowG(int r, int m) {
    return (((r >> 3) & 3) << 8) + (m << 5) + (((r >> 5) << 3) | (r & 7));
}

// ---- SMEM byte layout -------------------------------------------------------
#define OF_AU   1024            // Whi tile 128xSTR u32 = 69632
#define OF_AL   70656           // Wlo tile 69632
#define OF_AX   140288          // Wx tile 128x20 u32 = 10240 (alias: dense W)
#define OF_BX0  150528          // x tile ping 64x20 u32 = 5120
#define OF_BX1  155648          // x tile pong 5120
#define OF_BU   160768          // h_hi tile 64xSTR = 34816 (alias: dense h)
#define OF_BL   195584          // h_lo tile 34816
#define SMEM_BYTES 230400

// ---------------------------------------------------------------------------
__global__ void prep_kernel(const float* __restrict__ x,
                            const float* __restrict__ Wih,
                            const float* __restrict__ Whhe,
                            const float* __restrict__ Whhd,
                            const float* __restrict__ dW)
{
    const int S1 = 2 * 1024 * 128;
    const int S2 = S1 + 1024 * 8;
    const int S3 = S2 + 2 * PLANE;
    const int S4 = S3 + 16 * 72;
    const int S5 = S4 + 48 * 128 * 64 * 8;
    const int S6 = S5 + 24 * 8 * 256;
    for (int i = blockIdx.x * blockDim.x + threadIdx.x; i < S6;
         i += gridDim.x * blockDim.x) {
        if (i < S1) {
            int which = i >> 17, j = i & 131071;
            int G = j >> 7, col = j & 127;
            const float* W = which ? Whhd : Whhe;
            u16 ha, la, hb, lb;
            split16(W[G * HID + 2 * col], ha, la);
            split16(W[G * HID + 2 * col + 1], hb, lb);
            g_Wh[which][G][col] = (u32)ha | ((u32)hb << 16);
            g_Wl[which][G][col] = (u32)la | ((u32)lb << 16);
        } else if (i < S2) {
            int j = i - S1, G = j >> 3, cp = j & 7;
            u16 ha, la, hb, lb;
            split16(Wih[G * 16 + 2 * cp], ha, la);
            split16(Wih[G * 16 + 2 * cp + 1], hb, lb);
            g_Wxh[G][cp] = (u32)ha | ((u32)hb << 16);
            g_Wxl[G][cp] = (u32)la | ((u32)lb << 16);
        } else if (i < S3) {
            int j = i - S2;
            if (j < PLANE) g_hHi[0][j] = 0; else g_hLo[0][j - PLANE] = 0;
        } else if (i < S4) {
            g_ctr[i - S3] = 0;
        } else if (i < S5) {
            int j = i - S4;
            int cp = j & 7, n = (j >> 3) & 63, sq = (j >> 9) & 127, t = j >> 16;
            u16 ha, la, hb, lb;
            int ng = sq * 64 + n;
            split16(x[(ng * 16 + 2 * cp) * 48 + t], ha, la);
            split16(x[(ng * 16 + 2 * cp + 1) * 48 + t], hb, lb);
            int sc = ((cp & 3) << 1) + (cp >> 2);      // scol within 8-group
            u32* dst = g_xT + ((t * 128 + sq) * 64 + n) * 16;
            dst[sc]     = (u32)ha | ((u32)hb << 16);
            dst[8 + sc] = (u32)la | ((u32)lb << 16);
        } else {
            int j = i - S5;
            int k = j & 255, o = (j >> 8) & 7, td = j >> 11;
            g_dWp[td * 2048 + o * 256 + 2 * scol(k >> 1) + (k & 1)] =
                dW[td * 2048 + o * 256 + k];
        }
    }
}

// ---------------------------------------------------------------------------
__device__ __forceinline__ void loadA(int which, int m, int tid, char* sm)
{
    u32* AuHi = (u32*)(sm + OF_AU);
    u32* AuLo = (u32*)(sm + OF_AL);
    u32* Ax   = (u32*)(sm + OF_AX);
    for (int i = tid; i < 128 * 128; i += 512) {
        int r = i >> 7, j = i & 127;
        int G = rowG(r, m);
        int col = scol(j);
        AuHi[r * STR + col] = g_Wh[which][G][j];
        AuLo[r * STR + col] = g_Wl[which][G][j];
    }
    if (which == 0) {
        for (int i = tid; i < 128 * 8; i += 512) {
            int r = i >> 3, j = i & 7;
            int G = rowG(r, m);
            int col = ((j & 3) << 1) + (j >> 2);
            Ax[r * 20 + col]     = g_Wxh[G][j];
            Ax[r * 20 + 8 + col] = g_Wxl[G][j];
        }
    }
}

// cp.async one 32KB h plane tile with 512 threads (init / loop-bottom paths)
__device__ __forceinline__ void copyPlane(u32 sb, int dstOff,
                                          const u32* __restrict__ src, int tid)
{
    int n = tid >> 3;
    #pragma unroll
    for (int it = 0; it < 4; ++it) {
        int c = (tid & 7) + it * 8;
        cpa16(sb + dstOff + (n * STR + c * 4) * 4, src + n * 128 + c * 4);
    }
}
// same, with 256 threads (copy warps 8-15, p = tid-256)
__device__ __forceinline__ void copyPlane256(u32 sb, int dstOff,
                                             const u32* __restrict__ src, int p)
{
    int n = p >> 2;
    #pragma unroll
    for (int it = 0; it < 8; ++it) {
        int c = (p & 3) + it * 4;
        cpa16(sb + dstOff + (n * STR + c * 4) * 4, src + n * 128 + c * 4);
    }
}
__device__ __forceinline__ void copyX(u32 sb, int dstOff,
                                      const u32* __restrict__ src, int tid)
{
    if (tid < 256) {
        int n = tid >> 2, c4 = tid & 3;
        cpa16(sb + dstOff + (n * 20 + c4 * 4) * 4, src + n * 16 + c4 * 4);
    }
}
__device__ __forceinline__ void copyX256(u32 sb, int dstOff,
                                         const u32* __restrict__ src, int p)
{
    int n = p >> 2, c4 = p & 3;
    cpa16(sb + dstOff + (n * 20 + c4 * 4) * 4, src + n * 16 + c4 * 4);
}

// ---------------------------------------------------------------------------
__global__ void __launch_bounds__(512, 1)
lstm_mma(const float* __restrict__ enc_b, const float* __restrict__ dec_b,
         const float* __restrict__ db, float* __restrict__ out)
{
    extern __shared__ char sm[];
    const u32 sb = smem_u32(sm);
    u32*   AuHi   = (u32*)(sm + OF_AU);
    u32*   AuLo   = (u32*)(sm + OF_AL);
    u32*   Ax     = (u32*)(sm + OF_AX);
    u32*   BuHi   = (u32*)(sm + OF_BU);
    u32*   BuLo   = (u32*)(sm + OF_BL);

    const int tid = threadIdx.x, w = tid >> 5, lane = tid & 31;
    const int m = blockIdx.x & 7, s = blockIdx.x >> 3;
    const int gr = lane >> 2, tq = lane & 3;
    const bool isMMA = (w < 8);
    const int mg = w & 3, ns = (w >> 2) & 1;    // MMA warp = m32 x n32 tile
    const int r0 = mg * 32, nb0 = ns * 32;
    const int kkg = m * 32 + mg * 8 + gr;       // this thread's global k row

    loadA(0, m, tid, sm);
    float bi = enc_b[kkg],       bf = enc_b[256 + kkg];
    float bg = enc_b[512 + kkg], bo = enc_b[768 + kkg];
    copyPlane(sb, OF_BU, g_hHi[0] + (size_t)(s * 8) * 64 * 128, tid);
    copyPlane(sb, OF_BL, g_hLo[0] + (size_t)(s * 8) * 64 * 128, tid);
    copyX(sb, OF_BX0, g_xT + (size_t)(0 * 128 + s * 8) * 1024, tid);
    CPA_COMMIT(); CPA_WAIT0();
    __syncthreads();

    float cst[8][8];
    #pragma unroll
    for (int q = 0; q < 8; ++q)
        #pragma unroll
        for (int j = 0; j < 8; ++j) cst[q][j] = 0.f;

    // h store constants (cell (kk, n): pair partner = lane^4)
    const int hcol  = m * 16 + scol(mg * 4 + (gr >> 1));
    const bool evenk = (gr & 1) == 0;
    const u32 psel  = evenk ? 0x5410u : 0x7632u;

    int pp = 0;

    for (int t = 0; t < 72; ++t) {
        #pragma unroll 1
        for (int q = 0; q < 8; ++q) {
            const int sq = s * 8 + q;
            const int bxOff = (q & 1) ? OF_BX1 : OF_BX0;

            float acc[2][4][4];
            if (isMMA) {
                #pragma unroll
                for (int mi = 0; mi < 2; ++mi)
                    #pragma unroll
                    for (int nt = 0; nt < 4; ++nt)
                        #pragma unroll
                        for (int j = 0; j < 4; ++j) acc[mi][nt][j] = 0.f;

                if (t < 48) {
                    u32* Bx = (u32*)(sm + bxOff);
                    uint2 AH[4], AL[4], BH[4], BL[4];
                    #pragma unroll
                    for (int rr = 0; rr < 4; ++rr) {
                        AH[rr] = *(const uint2*)&Ax[(r0 + 8 * rr + gr) * 20 + tq * 2];
                        AL[rr] = *(const uint2*)&Ax[(r0 + 8 * rr + gr) * 20 + 8 + tq * 2];
                    }
                    #pragma unroll
                    for (int nt = 0; nt < 4; ++nt) {
                        BH[nt] = *(const uint2*)&Bx[(nb0 + nt * 8 + gr) * 20 + tq * 2];
                        BL[nt] = *(const uint2*)&Bx[(nb0 + nt * 8 + gr) * 20 + 8 + tq * 2];
                    }
                    #pragma unroll
                    for (int mi = 0; mi < 2; ++mi)
                        #pragma unroll
                        for (int nt = 0; nt < 4; ++nt) {
                            mma16816(acc[mi][nt], AH[2*mi].x, AH[2*mi+1].x,
                                     AH[2*mi].y, AH[2*mi+1].y, BH[nt].x, BH[nt].y);
                            mma16816(acc[mi][nt], AH[2*mi].x, AH[2*mi+1].x,
                                     AH[2*mi].y, AH[2*mi+1].y, BL[nt].x, BL[nt].y);
                            mma16816(acc[mi][nt], AL[2*mi].x, AL[2*mi+1].x,
                                     AL[2*mi].y, AL[2*mi+1].y, BH[nt].x, BH[nt].y);
                        }
                }
                {
                    const u32* ah = AuHi + (r0 + gr) * STR + tq * 2;
                    const u32* al = AuLo + (r0 + gr) * STR + tq * 2;
                    const u32* bh = BuHi + (nb0 + gr) * STR + tq * 2;
                    const u32* bl = BuLo + (nb0 + gr) * STR + tq * 2;
                    #pragma unroll 2
                    for (int ks = 0; ks < 16; ++ks) {
                        uint2 AH[4], AL[4], BH[4], BL[4];
                        #pragma unroll
                        for (int rr = 0; rr < 4; ++rr) {
                            AH[rr] = *(const uint2*)(ah + rr * 8 * STR + ks * 8);
                            AL[rr] = *(const uint2*)(al + rr * 8 * STR + ks * 8);
                            BH[rr] = *(const uint2*)(bh + rr * 8 * STR + ks * 8);
                            BL[rr] = *(const uint2*)(bl + rr * 8 * STR + ks * 8);
                        }
                        #pragma unroll
                        for (int mi = 0; mi < 2; ++mi)
                            #pragma unroll
                            for (int nt = 0; nt < 4; ++nt) {
                                mma16816(acc[mi][nt], AH[2*mi].x, AH[2*mi+1].x,
                                         AH[2*mi].y, AH[2*mi+1].y, BH[nt].x, BH[nt].y);
                                mma16816(acc[mi][nt], AH[2*mi].x, AH[2*mi+1].x,
                                         AH[2*mi].y, AH[2*mi+1].y, BL[nt].x, BL[nt].y);
                                mma16816(acc[mi][nt], AL[2*mi].x, AL[2*mi+1].x,
                                         AL[2*mi].y, AL[2*mi+1].y, BH[nt].x, BH[nt].y);
                            }
                    }
                }
            }
            __syncthreads();        // B reads done -> tiles may be overwritten

            if (!isMMA) {
                // copy warps: prefetch next chunk's tiles under the update
                if (q < 7) {
                    int p = tid - 256;
                    copyPlane256(sb, OF_BU,
                                 g_hHi[pp] + (size_t)(sq + 1) * 64 * 128, p);
                    copyPlane256(sb, OF_BL,
                                 g_hLo[pp] + (size_t)(sq + 1) * 64 * 128, p);
                    if (t < 48)
                        copyX256(sb, (q & 1) ? OF_BX0 : OF_BX1,
                                 g_xT + (size_t)(t * 128 + sq + 1) * 1024, p);
                    CPA_COMMIT();
                }
                CPA_WAIT0();
            } else {
                // ---- LSTM cell update fully in registers ----
                // acc[0][nt][0,1]=i, acc[0][nt][2,3]=f,
                // acc[1][nt][0,1]=g, acc[1][nt][2,3]=o
                u32 ps[8];
                #pragma unroll
                for (int nt = 0; nt < 4; ++nt)
                    #pragma unroll
                    for (int j = 0; j < 2; ++j) {
                        int ci = nt * 2 + j;
                        float gi = acc[0][nt][j]     + bi;
                        float gf = acc[0][nt][2 + j] + bf;
                        float gg = acc[1][nt][j]     + bg;
                        float go = acc[1][nt][2 + j] + bo;
                        float cn = sigf(gf) * cst[q][ci] + sigf(gi) * tanh_(gg);
                        cst[q][ci] = cn;
                        ps[ci] = packsplit(sigf(go) * tanh_(cn));
                    }
                u32* plane = (evenk ? g_hHi : g_hLo)[pp ^ 1];
                #pragma unroll
                for (int ci = 0; ci < 8; ++ci) {
                    u32 po = __shfl_xor_sync(0xFFFFFFFFu, ps[ci], 4);
                    u32 a  = evenk ? ps[ci] : po;
                    u32 b  = evenk ? po : ps[ci];
                    u32 word = prmt(a, b, psel);
                    int n = nb0 + (ci >> 1) * 8 + 2 * tq + (ci & 1);
                    plane[(size_t)(sq * 64 + n) * 128 + hcol] = word;
                }
            }
            __syncthreads();
        }

        // ---- slice barrier (8 peer CTAs) ----
        if (tid == 0) {
            __threadfence();
            atomicAdd(&g_ctr[s * 72 + t], 1);
            int v;
            do {
                asm volatile("ld.global.acquire.gpu.b32 %0, [%1];"
                             : "=r"(v) : "l"(&g_ctr[s * 72 + t]));
            } while (v < 8);
        }
        __syncthreads();
        pp ^= 1;

        // ---- decoder dense epilogue ----
        if (t >= 48) {
            int td = t - 48;
            const size_t hb = (size_t)(s * 8 + m) * 64 * 128;
            copyPlane(sb, OF_BU, g_hHi[pp] + hb, tid);
            copyPlane(sb, OF_BL, g_hLo[pp] + hb, tid);
            float* wstage = (float*)(sm + OF_AX);
            {
                float4 wv = *(const float4*)(g_dWp + td * 2048 + tid * 4);
                int o = tid >> 6, k4 = tid & 63;
                *(float4*)&wstage[o * 260 + k4 * 4] = wv;
            }
            CPA_COMMIT(); CPA_WAIT0();
            __syncthreads();
            int n_l = tid >> 3, o2 = tid & 7;
            const u32* hh = BuHi + n_l * STR;
            const u32* hl = BuLo + n_l * STR;
            const float2* wr = (const float2*)&wstage[o2 * 260];
            float a = __ldg(db + td * 8 + o2);
            #pragma unroll 8
            for (int pi = 0; pi < 128; ++pi) {
                float2 ph = bf2f(hh[pi]), pl = bf2f(hl[pi]);
                float2 wv = wr[pi];
                a = fmaf(ph.x + pl.x, wv.x, a);
                a = fmaf(ph.y + pl.y, wv.y, a);
            }
            out[((size_t)(s * 512 + m * 64 + n_l) * 8 + o2) * 24 + td] = a;
            __syncthreads();
        }

        if (t == 47) {
            loadA(1, m, tid, sm);
            bi = dec_b[kkg];       bf = dec_b[256 + kkg];
            bg = dec_b[512 + kkg]; bo = dec_b[768 + kkg];
            #pragma unroll
            for (int q = 0; q < 8; ++q)
                #pragma unroll
                for (int j = 0; j < 8; ++j) cst[q][j] = 0.f;
        }

        if (t < 71) {       // copies for (t+1, q=0)
            copyPlane(sb, OF_BU, g_hHi[pp] + (size_t)(s * 8) * 64 * 128, tid);
            copyPlane(sb, OF_BL, g_hLo[pp] + (size_t)(s * 8) * 64 * 128, tid);
            if (t < 47)
                copyX(sb, OF_BX0,
                      g_xT + (size_t)((t + 1) * 128 + s * 8) * 1024, tid);
            CPA_COMMIT(); CPA_WAIT0();
        }
        __syncthreads();
    }
}

// ---------------------------------------------------------------------------
extern "C" void kernel_launch(void* const* d_in, const int* in_sizes, int n_in,
                              void* d_out, int out_size)
{
    (void)in_sizes; (void)n_in; (void)out_size;
    const float* x       = (const float*)d_in[0];
    const float* enc_Wih = (const float*)d_in[1];
    const float* enc_Whh = (const float*)d_in[2];
    const float* enc_b   = (const float*)d_in[3];
    const float* dec_Whh = (const float*)d_in[4];
    const float* dec_b   = (const float*)d_in[5];
    const float* dense_W = (const float*)d_in[6];
    const float* dense_b = (const float*)d_in[7];
    float* out = (float*)d_out;

    cudaFuncSetAttribute(lstm_mma,
                         cudaFuncAttributeMaxDynamicSharedMemorySize, SMEM_BYTES);

    prep_kernel<<<2048, 256>>>(x, enc_Wih, enc_Whh, dec_Whh, dense_W);
    lstm_mma<<<128, 512, SMEM_BYTES>>>(enc_b, dec_b, dense_b, out);
}